// round 12
// baseline (speedup 1.0000x reference)
#include <cuda_runtime.h>
#include <cstdint>

#define N_NODES 100000
#define N_EDGES 1250000
#define IN_CH   128
#define HID_CH  64
#define CLS_CH  32
#define SCAN_B  1024
#define NB      98        // ceil(N_NODES / SCAN_B)

// ---------------- scratch (device globals; alloc-free rule) ----------------
__device__ __align__(16) float g_h1  [(size_t)N_NODES * HID_CH];
__device__ __align__(16) float g_act1[(size_t)N_NODES * HID_CH];
__device__ __align__(16) float g_m2  [(size_t)N_NODES * CLS_CH];
__device__ int g_deg   [N_NODES];          // invariant: zero at kernel_launch entry
__device__ int g_incl  [N_NODES];
__device__ int g_off   [N_NODES + 1];
__device__ int g_cursor[N_NODES];
__device__ int g_bsum  [128];
__device__ int g_csr_src[N_EDGES];

// ---------------- packed f32x2 helpers ----------------
__device__ __forceinline__ unsigned long long pack2(float a, float b) {
    unsigned long long r;
    asm("mov.b64 %0, {%1, %2};" : "=l"(r) : "f"(a), "f"(b));
    return r;
}
__device__ __forceinline__ unsigned long long fma2(unsigned long long a,
                                                   unsigned long long b,
                                                   unsigned long long c) {
    unsigned long long d;
    asm("fma.rn.f32x2 %0, %1, %2, %3;" : "=l"(d) : "l"(a), "l"(b), "l"(c));
    return d;
}
__device__ __forceinline__ float2 ull2f2(unsigned long long u) {
    float2 f;
    asm("mov.b64 {%0, %1}, %2;" : "=f"(f.x), "=f"(f.y) : "l"(u));
    return f;
}

// ---------------- hist: degree histogram into pre-zeroed g_deg ----------------
__global__ void k_hist(const int* __restrict__ dst) {
    int e = blockIdx.x * blockDim.x + threadIdx.x;
    if (e < N_EDGES) atomicAdd(&g_deg[__ldg(dst + e)], 1);
}

// ---------------- scan1: per-block inclusive scan (warp-shuffle) ----------------
__global__ __launch_bounds__(SCAN_B) void k_scan1() {
    __shared__ int swarp[32];
    int tid = threadIdx.x;
    int lane = tid & 31, wid = tid >> 5;
    int i = blockIdx.x * SCAN_B + tid;
    int v = (i < N_NODES) ? g_deg[i] : 0;
    int x = v;
#pragma unroll
    for (int o = 1; o < 32; o <<= 1) {
        int n = __shfl_up_sync(0xffffffffu, x, o);
        if (lane >= o) x += n;
    }
    if (lane == 31) swarp[wid] = x;
    __syncthreads();
    if (wid == 0) {
        int w = swarp[lane];
#pragma unroll
        for (int o = 1; o < 32; o <<= 1) {
            int n = __shfl_up_sync(0xffffffffu, w, o);
            if (lane >= o) w += n;
        }
        swarp[lane] = w;
    }
    __syncthreads();
    int incl = x + (wid > 0 ? swarp[wid - 1] : 0);
    if (i < N_NODES) g_incl[i] = incl;
    if (tid == SCAN_B - 1) g_bsum[blockIdx.x] = incl;
}

// ---------------- scan23: block-base reduce + final offsets + cursor prime ----------------
__global__ __launch_bounds__(SCAN_B) void k_scan23() {
    __shared__ int sred[32];
    __shared__ int s_base;
    int tid = threadIdx.x;
    int v = (tid < blockIdx.x) ? g_bsum[tid] : 0;   // blockIdx.x <= 97 < 128
#pragma unroll
    for (int o = 16; o; o >>= 1) v += __shfl_down_sync(0xffffffffu, v, o);
    if ((tid & 31) == 0) sred[tid >> 5] = v;
    __syncthreads();
    if (tid < 32) {
        int w = sred[tid];
#pragma unroll
        for (int o = 16; o; o >>= 1) w += __shfl_down_sync(0xffffffffu, w, o);
        if (tid == 0) s_base = w;
    }
    __syncthreads();
    int i = blockIdx.x * SCAN_B + tid;
    if (i < N_NODES) {
        int d = g_deg[i];
        int off = g_incl[i] - d + s_base;
        g_off[i] = off;
        g_cursor[i] = off;
        if (i == N_NODES - 1) g_off[N_NODES] = off + d;
    }
}

// ---------------- fill: cursor pre-primed to offset ----------------
__global__ void k_fill(const int* __restrict__ src, const int* __restrict__ dst) {
    int e = blockIdx.x * blockDim.x + threadIdx.x;
    if (e >= N_EDGES) return;
    int d = __ldg(dst + e);
    int pos = atomicAdd(&g_cursor[d], 1);
    g_csr_src[pos] = __ldg(src + e);
}

// ---------------- gemm1: h1 = x @ W1 (128->64), 8x8 thread tile ----------------
// block: 128 threads, tile 128 rows x 64 cols, BK=16, double-buffered.
// per k-step/thread: 4 LDS.128 (16 crossbar cyc/warp) vs 32 FFMA2 (16 fma cyc) - balanced.
#define BM 128
#define BK 16
#define SA_STRIDE 136     // 128 + 8 pad floats
__global__ __launch_bounds__(128) void k_gemm1(const float* __restrict__ x,
                                               const float* __restrict__ W1) {
    __shared__ __align__(16) float sA[2][BK][SA_STRIDE];   // 17.4 KB, k-major
    __shared__ __align__(16) float sW[2][BK][HID_CH];      // 8 KB
    int tid = threadIdx.x;
    int ty = tid >> 3;            // 0..15 : rows ty*8 .. +7
    int tx = tid & 7;             // 0..7  : cols tx*8 .. +7
    int row0 = blockIdx.x * BM;
    // A loader: 128 rows x 16 cols per chunk; thread loads 1 float4 in each of 4 row-groups
    int ar = tid >> 2, ac4 = tid & 3;            // ar 0..31
    int gr0 = min(row0 + ar,      N_NODES - 1);
    int gr1 = min(row0 + ar + 32, N_NODES - 1);
    int gr2 = min(row0 + ar + 64, N_NODES - 1);
    int gr3 = min(row0 + ar + 96, N_NODES - 1);
    const float4* xr0 = reinterpret_cast<const float4*>(x + (size_t)gr0 * IN_CH) + ac4;
    const float4* xr1 = reinterpret_cast<const float4*>(x + (size_t)gr1 * IN_CH) + ac4;
    const float4* xr2 = reinterpret_cast<const float4*>(x + (size_t)gr2 * IN_CH) + ac4;
    const float4* xr3 = reinterpret_cast<const float4*>(x + (size_t)gr3 * IN_CH) + ac4;
    // W loader: 16 k x 64 cols = 256 float4; thread loads f = tid and tid+128
    int wk0 = tid >> 4, wc0 = tid & 15;          // k 0..7
    int wk1 = wk0 + 8;                           // k 8..15

    float4 pa0 = __ldg(xr0), pa1 = __ldg(xr1), pa2 = __ldg(xr2), pa3 = __ldg(xr3);
    float4 pw0 = __ldg(reinterpret_cast<const float4*>(W1 + (size_t)wk0 * HID_CH) + wc0);
    float4 pw1 = __ldg(reinterpret_cast<const float4*>(W1 + (size_t)wk1 * HID_CH) + wc0);

    unsigned long long acc[4][8];   // [rowpair][col]
#pragma unroll
    for (int i = 0; i < 4; i++)
#pragma unroll
        for (int j = 0; j < 8; j++) acc[i][j] = 0ull;

#pragma unroll 1
    for (int ch = 0; ch < IN_CH / BK; ch++) {
        int s = ch & 1;
        // store prefetched A (transposed to k-major) and W
#pragma unroll
        for (int t = 0; t < 4; t++) {
            float va = (t == 0) ? pa0.x : (t == 1) ? pa0.y : (t == 2) ? pa0.z : pa0.w;
            float vb = (t == 0) ? pa1.x : (t == 1) ? pa1.y : (t == 2) ? pa1.z : pa1.w;
            float vc = (t == 0) ? pa2.x : (t == 1) ? pa2.y : (t == 2) ? pa2.z : pa2.w;
            float vd = (t == 0) ? pa3.x : (t == 1) ? pa3.y : (t == 2) ? pa3.z : pa3.w;
            sA[s][ac4 * 4 + t][ar]      = va;
            sA[s][ac4 * 4 + t][ar + 32] = vb;
            sA[s][ac4 * 4 + t][ar + 64] = vc;
            sA[s][ac4 * 4 + t][ar + 96] = vd;
        }
        *reinterpret_cast<float4*>(&sW[s][wk0][wc0 * 4]) = pw0;
        *reinterpret_cast<float4*>(&sW[s][wk1][wc0 * 4]) = pw1;
        __syncthreads();
        if (ch < IN_CH / BK - 1) {
            int k4 = (ch + 1) * BK / 4;
            pa0 = __ldg(xr0 + k4);
            pa1 = __ldg(xr1 + k4);
            pa2 = __ldg(xr2 + k4);
            pa3 = __ldg(xr3 + k4);
            pw0 = __ldg(reinterpret_cast<const float4*>(
                            W1 + (size_t)((ch + 1) * BK + wk0) * HID_CH) + wc0);
            pw1 = __ldg(reinterpret_cast<const float4*>(
                            W1 + (size_t)((ch + 1) * BK + wk1) * HID_CH) + wc0);
        }
#pragma unroll
        for (int k = 0; k < BK; k++) {
            ulonglong2 aA = *reinterpret_cast<const ulonglong2*>(&sA[s][k][ty * 8]);
            ulonglong2 aB = *reinterpret_cast<const ulonglong2*>(&sA[s][k][ty * 8 + 4]);
            float4 w0 = *reinterpret_cast<const float4*>(&sW[s][k][tx * 8]);
            float4 w1 = *reinterpret_cast<const float4*>(&sW[s][k][tx * 8 + 4]);
            unsigned long long ww0 = pack2(w0.x, w0.x);
            unsigned long long ww1 = pack2(w0.y, w0.y);
            unsigned long long ww2 = pack2(w0.z, w0.z);
            unsigned long long ww3 = pack2(w0.w, w0.w);
            unsigned long long ww4 = pack2(w1.x, w1.x);
            unsigned long long ww5 = pack2(w1.y, w1.y);
            unsigned long long ww6 = pack2(w1.z, w1.z);
            unsigned long long ww7 = pack2(w1.w, w1.w);
            unsigned long long r0 = aA.x, r1 = aA.y, r2 = aB.x, r3 = aB.y;
            acc[0][0] = fma2(r0, ww0, acc[0][0]);
            acc[0][1] = fma2(r0, ww1, acc[0][1]);
            acc[0][2] = fma2(r0, ww2, acc[0][2]);
            acc[0][3] = fma2(r0, ww3, acc[0][3]);
            acc[0][4] = fma2(r0, ww4, acc[0][4]);
            acc[0][5] = fma2(r0, ww5, acc[0][5]);
            acc[0][6] = fma2(r0, ww6, acc[0][6]);
            acc[0][7] = fma2(r0, ww7, acc[0][7]);
            acc[1][0] = fma2(r1, ww0, acc[1][0]);
            acc[1][1] = fma2(r1, ww1, acc[1][1]);
            acc[1][2] = fma2(r1, ww2, acc[1][2]);
            acc[1][3] = fma2(r1, ww3, acc[1][3]);
            acc[1][4] = fma2(r1, ww4, acc[1][4]);
            acc[1][5] = fma2(r1, ww5, acc[1][5]);
            acc[1][6] = fma2(r1, ww6, acc[1][6]);
            acc[1][7] = fma2(r1, ww7, acc[1][7]);
            acc[2][0] = fma2(r2, ww0, acc[2][0]);
            acc[2][1] = fma2(r2, ww1, acc[2][1]);
            acc[2][2] = fma2(r2, ww2, acc[2][2]);
            acc[2][3] = fma2(r2, ww3, acc[2][3]);
            acc[2][4] = fma2(r2, ww4, acc[2][4]);
            acc[2][5] = fma2(r2, ww5, acc[2][5]);
            acc[2][6] = fma2(r2, ww6, acc[2][6]);
            acc[2][7] = fma2(r2, ww7, acc[2][7]);
            acc[3][0] = fma2(r3, ww0, acc[3][0]);
            acc[3][1] = fma2(r3, ww1, acc[3][1]);
            acc[3][2] = fma2(r3, ww2, acc[3][2]);
            acc[3][3] = fma2(r3, ww3, acc[3][3]);
            acc[3][4] = fma2(r3, ww4, acc[3][4]);
            acc[3][5] = fma2(r3, ww5, acc[3][5]);
            acc[3][6] = fma2(r3, ww6, acc[3][6]);
            acc[3][7] = fma2(r3, ww7, acc[3][7]);
        }
    }
#pragma unroll
    for (int rp = 0; rp < 4; rp++) {
        int r = row0 + ty * 8 + rp * 2;
        float2 c0 = ull2f2(acc[rp][0]), c1 = ull2f2(acc[rp][1]);
        float2 c2 = ull2f2(acc[rp][2]), c3 = ull2f2(acc[rp][3]);
        float2 c4 = ull2f2(acc[rp][4]), c5 = ull2f2(acc[rp][5]);
        float2 c6 = ull2f2(acc[rp][6]), c7 = ull2f2(acc[rp][7]);
        if (r < N_NODES) {
            float* o = g_h1 + (size_t)r * HID_CH + tx * 8;
            *reinterpret_cast<float4*>(o)     = make_float4(c0.x, c1.x, c2.x, c3.x);
            *reinterpret_cast<float4*>(o + 4) = make_float4(c4.x, c5.x, c6.x, c7.x);
        }
        if (r + 1 < N_NODES) {
            float* o = g_h1 + (size_t)(r + 1) * HID_CH + tx * 8;
            *reinterpret_cast<float4*>(o)     = make_float4(c0.y, c1.y, c2.y, c3.y);
            *reinterpret_cast<float4*>(o + 4) = make_float4(c4.y, c5.y, c6.y, c7.y);
        }
    }
}

// ---------------- agg1: act1 = relu(A @ h1 + b1); 2 edges per warp-load ----------------
__global__ __launch_bounds__(256) void k_agg1(const float* __restrict__ b1) {
    int t = blockIdx.x * 256 + threadIdx.x;
    int node = t >> 5;
    if (node >= N_NODES) return;
    int lane = t & 31;
    int half = lane >> 4;
    int q    = lane & 15;

    int beg = g_off[node];
    int dg  = g_off[node + 1] - beg;
    if (lane == 0) g_deg[node] = 0;      // restore zero-invariant for next call

    const float4* h1v = reinterpret_cast<const float4*>(g_h1);
    float4 a0{0,0,0,0}, a1{0,0,0,0}, a2{0,0,0,0}, a3{0,0,0,0};

    for (int base = 0; base < dg; base += 32) {
        int rem = dg - base;
        int idx = (lane < rem) ? __ldg(g_csr_src + beg + base + lane) : 0;
#pragma unroll
        for (int j = 0; j < 16; j += 4) {
            if (2 * j >= rem) break;     // warp-uniform
            int s0 = __shfl_sync(0xffffffffu, idx, 2 * j + 0 + half);
            int s1 = __shfl_sync(0xffffffffu, idx, 2 * j + 2 + half);
            int s2 = __shfl_sync(0xffffffffu, idx, 2 * j + 4 + half);
            int s3 = __shfl_sync(0xffffffffu, idx, 2 * j + 6 + half);
            if (2 * j + 0 + half < rem) {
                float4 v = __ldg(h1v + (size_t)s0 * 16 + q);
                a0.x += v.x; a0.y += v.y; a0.z += v.z; a0.w += v.w;
            }
            if (2 * j + 2 + half < rem) {
                float4 v = __ldg(h1v + (size_t)s1 * 16 + q);
                a1.x += v.x; a1.y += v.y; a1.z += v.z; a1.w += v.w;
            }
            if (2 * j + 4 + half < rem) {
                float4 v = __ldg(h1v + (size_t)s2 * 16 + q);
                a2.x += v.x; a2.y += v.y; a2.z += v.z; a2.w += v.w;
            }
            if (2 * j + 6 + half < rem) {
                float4 v = __ldg(h1v + (size_t)s3 * 16 + q);
                a3.x += v.x; a3.y += v.y; a3.z += v.z; a3.w += v.w;
            }
        }
    }
    float4 A;
    A.x = (a0.x + a1.x) + (a2.x + a3.x);
    A.y = (a0.y + a1.y) + (a2.y + a3.y);
    A.z = (a0.z + a1.z) + (a2.z + a3.z);
    A.w = (a0.w + a1.w) + (a2.w + a3.w);
    A.x += __shfl_xor_sync(0xffffffffu, A.x, 16);
    A.y += __shfl_xor_sync(0xffffffffu, A.y, 16);
    A.z += __shfl_xor_sync(0xffffffffu, A.z, 16);
    A.w += __shfl_xor_sync(0xffffffffu, A.w, 16);
    if (half == 0) {
        float4 b = __ldg(reinterpret_cast<const float4*>(b1) + q);
        A.x = fmaxf(A.x + b.x, 0.f);
        A.y = fmaxf(A.y + b.y, 0.f);
        A.z = fmaxf(A.z + b.z, 0.f);
        A.w = fmaxf(A.w + b.w, 0.f);
        reinterpret_cast<float4*>(g_act1)[(size_t)node * 16 + q] = A;
    }
}

// ---------------- gemm2: m2 = act1 @ W2 (64->32), double-buffered (R8-proven) ----------------
#define SA_PAD 136
__global__ __launch_bounds__(256) void k_gemm2(const float* __restrict__ W2) {
    __shared__ __align__(16) float sA[2][BK][SA_PAD];
    __shared__ __align__(16) float sW[2][BK][CLS_CH];
    int tid = threadIdx.x;
    int tx = tid & 15;
    int ty = tid >> 4;
    int row0 = blockIdx.x * BM;
    int ar = tid >> 2, ac4 = tid & 3;
    int wk = tid >> 3, wc4 = tid & 7;
    int gr0 = min(row0 + ar,      N_NODES - 1);
    int gr1 = min(row0 + ar + 64, N_NODES - 1);

    float4 pa0, pa1, pw;
    pa0 = *reinterpret_cast<const float4*>(g_act1 + (size_t)gr0 * HID_CH + ac4 * 4);
    pa1 = *reinterpret_cast<const float4*>(g_act1 + (size_t)gr1 * HID_CH + ac4 * 4);
    if (tid < 128)
        pw = __ldg(reinterpret_cast<const float4*>(W2 + (size_t)wk * CLS_CH) + wc4);

    unsigned long long acc[4][2];
#pragma unroll
    for (int i = 0; i < 4; i++) { acc[i][0] = 0ull; acc[i][1] = 0ull; }

#pragma unroll 1
    for (int ch = 0; ch < HID_CH / BK; ch++) {
        int s = ch & 1;
        sA[s][ac4 * 4 + 0][ar] = pa0.x;
        sA[s][ac4 * 4 + 1][ar] = pa0.y;
        sA[s][ac4 * 4 + 2][ar] = pa0.z;
        sA[s][ac4 * 4 + 3][ar] = pa0.w;
        sA[s][ac4 * 4 + 0][ar + 64] = pa1.x;
        sA[s][ac4 * 4 + 1][ar + 64] = pa1.y;
        sA[s][ac4 * 4 + 2][ar + 64] = pa1.z;
        sA[s][ac4 * 4 + 3][ar + 64] = pa1.w;
        if (tid < 128)
            *reinterpret_cast<float4*>(&sW[s][wk][wc4 * 4]) = pw;
        __syncthreads();
        if (ch < HID_CH / BK - 1) {
            int kofs = (ch + 1) * BK;
            pa0 = *reinterpret_cast<const float4*>(
                g_act1 + (size_t)gr0 * HID_CH + kofs + ac4 * 4);
            pa1 = *reinterpret_cast<const float4*>(
                g_act1 + (size_t)gr1 * HID_CH + kofs + ac4 * 4);
            if (tid < 128)
                pw = __ldg(reinterpret_cast<const float4*>(
                               W2 + (size_t)(kofs + wk) * CLS_CH) + wc4);
        }
#pragma unroll
        for (int k = 0; k < BK; k++) {
            ulonglong2 aA = *reinterpret_cast<const ulonglong2*>(&sA[s][k][ty * 8]);
            ulonglong2 aB = *reinterpret_cast<const ulonglong2*>(&sA[s][k][ty * 8 + 4]);
            float2 wv = *reinterpret_cast<const float2*>(&sW[s][k][tx * 2]);
            unsigned long long w0 = pack2(wv.x, wv.x);
            unsigned long long w1 = pack2(wv.y, wv.y);
            acc[0][0] = fma2(aA.x, w0, acc[0][0]);
            acc[0][1] = fma2(aA.x, w1, acc[0][1]);
            acc[1][0] = fma2(aA.y, w0, acc[1][0]);
            acc[1][1] = fma2(aA.y, w1, acc[1][1]);
            acc[2][0] = fma2(aB.x, w0, acc[2][0]);
            acc[2][1] = fma2(aB.x, w1, acc[2][1]);
            acc[3][0] = fma2(aB.y, w0, acc[3][0]);
            acc[3][1] = fma2(aB.y, w1, acc[3][1]);
        }
    }
#pragma unroll
    for (int rp = 0; rp < 4; rp++) {
        int r = row0 + ty * 8 + rp * 2;
        float2 c0 = ull2f2(acc[rp][0]), c1 = ull2f2(acc[rp][1]);
        if (r < N_NODES) {
            float2 lo = make_float2(c0.x, c1.x);
            *reinterpret_cast<float2*>(g_m2 + (size_t)r * CLS_CH + tx * 2) = lo;
        }
        if (r + 1 < N_NODES) {
            float2 hi = make_float2(c0.y, c1.y);
            *reinterpret_cast<float2*>(g_m2 + (size_t)(r + 1) * CLS_CH + tx * 2) = hi;
        }
    }
}

// ---------------- agg2: out = sigmoid(A @ m2 + b2); 4 edges per warp-load ----------------
__global__ __launch_bounds__(256) void k_agg2(const float* __restrict__ b2,
                                              float* __restrict__ out) {
    int t = blockIdx.x * 256 + threadIdx.x;
    int node = t >> 5;
    if (node >= N_NODES) return;
    int lane = t & 31;
    int grp = lane >> 3;
    int q   = lane & 7;

    int beg = g_off[node];
    int dg  = g_off[node + 1] - beg;

    const float4* m2v = reinterpret_cast<const float4*>(g_m2);
    float4 a0{0,0,0,0}, a1{0,0,0,0}, a2{0,0,0,0}, a3{0,0,0,0};

    for (int base = 0; base < dg; base += 32) {
        int rem = dg - base;
        int idx = (lane < rem) ? __ldg(g_csr_src + beg + base + lane) : 0;
#pragma unroll
        for (int j = 0; j < 8; j += 4) {
            if (4 * j >= rem) break;     // warp-uniform
            int s0 = __shfl_sync(0xffffffffu, idx, 4 * (j + 0) + grp);
            int s1 = __shfl_sync(0xffffffffu, idx, 4 * (j + 1) + grp);
            int s2 = __shfl_sync(0xffffffffu, idx, 4 * (j + 2) + grp);
            int s3 = __shfl_sync(0xffffffffu, idx, 4 * (j + 3) + grp);
            if (4 * (j + 0) + grp < rem) {
                float4 v = __ldg(m2v + (size_t)s0 * 8 + q);
                a0.x += v.x; a0.y += v.y; a0.z += v.z; a0.w += v.w;
            }
            if (4 * (j + 1) + grp < rem) {
                float4 v = __ldg(m2v + (size_t)s1 * 8 + q);
                a1.x += v.x; a1.y += v.y; a1.z += v.z; a1.w += v.w;
            }
            if (4 * (j + 2) + grp < rem) {
                float4 v = __ldg(m2v + (size_t)s2 * 8 + q);
                a2.x += v.x; a2.y += v.y; a2.z += v.z; a2.w += v.w;
            }
            if (4 * (j + 3) + grp < rem) {
                float4 v = __ldg(m2v + (size_t)s3 * 8 + q);
                a3.x += v.x; a3.y += v.y; a3.z += v.z; a3.w += v.w;
            }
        }
    }
    float4 A;
    A.x = (a0.x + a1.x) + (a2.x + a3.x);
    A.y = (a0.y + a1.y) + (a2.y + a3.y);
    A.z = (a0.z + a1.z) + (a2.z + a3.z);
    A.w = (a0.w + a1.w) + (a2.w + a3.w);
    A.x += __shfl_xor_sync(0xffffffffu, A.x, 8);
    A.y += __shfl_xor_sync(0xffffffffu, A.y, 8);
    A.z += __shfl_xor_sync(0xffffffffu, A.z, 8);
    A.w += __shfl_xor_sync(0xffffffffu, A.w, 8);
    A.x += __shfl_xor_sync(0xffffffffu, A.x, 16);
    A.y += __shfl_xor_sync(0xffffffffu, A.y, 16);
    A.z += __shfl_xor_sync(0xffffffffu, A.z, 16);
    A.w += __shfl_xor_sync(0xffffffffu, A.w, 16);
    if (lane < 8) {
        float4 b = __ldg(reinterpret_cast<const float4*>(b2) + q);
        A.x = 1.f / (1.f + __expf(-(A.x + b.x)));
        A.y = 1.f / (1.f + __expf(-(A.y + b.y)));
        A.z = 1.f / (1.f + __expf(-(A.z + b.z)));
        A.w = 1.f / (1.f + __expf(-(A.w + b.w)));
        reinterpret_cast<float4*>(out)[(size_t)node * 8 + q] = A;
    }
}

extern "C" void kernel_launch(void* const* d_in, const int* in_sizes, int n_in,
                              void* d_out, int out_size) {
    const float* x  = (const float*)d_in[0];
    const int*   ei = (const int*)  d_in[1];
    const float* W1 = (const float*)d_in[2];
    const float* b1 = (const float*)d_in[3];
    const float* W2 = (const float*)d_in[4];
    const float* b2 = (const float*)d_in[5];
    float* out = (float*)d_out;
    const int* src = ei;
    const int* dst = ei + N_EDGES;

    k_hist<<<(N_EDGES + 255) / 256, 256>>>(dst);
    k_scan1<<<NB, SCAN_B>>>();
    k_scan23<<<NB, SCAN_B>>>();
    k_gemm1<<<(N_NODES + BM - 1) / BM, 128>>>(x, W1);   // <- profiled (idx 3)
    k_fill<<<(N_EDGES + 255) / 256, 256>>>(src, dst);
    k_agg1<<<(N_NODES * 32 + 255) / 256, 256>>>(b1);
    k_gemm2<<<(N_NODES + BM - 1) / BM, 256>>>(W2);
    k_agg2<<<(N_NODES * 32 + 255) / 256, 256>>>(b2, out);
}

// round 14
// speedup vs baseline: 1.1124x; 1.1124x over previous
#include <cuda_runtime.h>
#include <cstdint>

#define N_NODES 100000
#define N_EDGES 1250000
#define IN_CH   128
#define HID_CH  64
#define CLS_CH  32
#define SCAN_B  1024
#define NB      98        // ceil(N_NODES / SCAN_B)

#define BM 128
#define BK 16
#define SA_PAD 136
#define G1_BLOCKS_TOTAL ((N_NODES + BM - 1) / BM)     // 782
#define G1A_BLOCKS 391                                 // rows [0, 50048)
#define G1B_BLOCKS (G1_BLOCKS_TOTAL - G1A_BLOCKS)      // 391, rows [50048, ...)
#define G1B_ROW0   (G1A_BLOCKS * BM)                   // 50048
#define HIST_BLOCKS ((N_EDGES + 255) / 256)            // 4883

// ---------------- scratch (device globals; alloc-free rule) ----------------
__device__ __align__(16) float g_h1  [(size_t)N_NODES * HID_CH];
__device__ __align__(16) float g_act1[(size_t)N_NODES * HID_CH];
__device__ __align__(16) float g_m2  [(size_t)N_NODES * CLS_CH];
__device__ int g_deg   [N_NODES];          // invariant: zero at kernel_launch entry
__device__ int g_incl  [N_NODES];
__device__ int g_off   [N_NODES + 1];
__device__ int g_cursor[N_NODES];
__device__ int g_bsum  [128];
__device__ int g_csr_src[N_EDGES];

// ---------------- packed f32x2 helpers ----------------
__device__ __forceinline__ unsigned long long pack2(float a, float b) {
    unsigned long long r;
    asm("mov.b64 %0, {%1, %2};" : "=l"(r) : "f"(a), "f"(b));
    return r;
}
__device__ __forceinline__ unsigned long long fma2(unsigned long long a,
                                                   unsigned long long b,
                                                   unsigned long long c) {
    unsigned long long d;
    asm("fma.rn.f32x2 %0, %1, %2, %3;" : "=l"(d) : "l"(a), "l"(b), "l"(c));
    return d;
}
__device__ __forceinline__ float2 ull2f2(unsigned long long u) {
    float2 f;
    asm("mov.b64 {%0, %1}, %2;" : "=f"(f.x), "=f"(f.y) : "l"(u));
    return f;
}

// ---------------- gemm1 body: rows [row0, row0+128) of h1 = x @ W1 (R8-proven) ----------------
__device__ __forceinline__ void gemm1_body(int row0, const float* __restrict__ x,
                                           const float* __restrict__ W1) {
    __shared__ __align__(16) float sA[2][BK][SA_PAD];    // 17.4 KB, k-major
    __shared__ __align__(16) float sW[2][BK][HID_CH];    // 8 KB
    int tid = threadIdx.x;
    int tx = tid & 15;         // cols tx*4 .. +3
    int ty = tid >> 4;         // rows ty*8 .. +7
    int ar = tid >> 2, ac4 = tid & 3;   // A-loader coords
    int wk = tid >> 4, wc4 = tid & 15;  // W-loader coords
    int gr0 = min(row0 + ar,      N_NODES - 1);
    int gr1 = min(row0 + ar + 64, N_NODES - 1);
    const float4* xr0 = reinterpret_cast<const float4*>(x + (size_t)gr0 * IN_CH) + ac4;
    const float4* xr1 = reinterpret_cast<const float4*>(x + (size_t)gr1 * IN_CH) + ac4;

    float4 pa0, pa1, pw;
    pa0 = __ldg(xr0);
    pa1 = __ldg(xr1);
    pw  = __ldg(reinterpret_cast<const float4*>(W1 + (size_t)wk * HID_CH) + wc4);

    unsigned long long acc[4][4];
#pragma unroll
    for (int i = 0; i < 4; i++)
#pragma unroll
        for (int j = 0; j < 4; j++) acc[i][j] = 0ull;

#pragma unroll 1
    for (int ch = 0; ch < IN_CH / BK; ch++) {
        int s = ch & 1;
        sA[s][ac4 * 4 + 0][ar] = pa0.x;
        sA[s][ac4 * 4 + 1][ar] = pa0.y;
        sA[s][ac4 * 4 + 2][ar] = pa0.z;
        sA[s][ac4 * 4 + 3][ar] = pa0.w;
        sA[s][ac4 * 4 + 0][ar + 64] = pa1.x;
        sA[s][ac4 * 4 + 1][ar + 64] = pa1.y;
        sA[s][ac4 * 4 + 2][ar + 64] = pa1.z;
        sA[s][ac4 * 4 + 3][ar + 64] = pa1.w;
        *reinterpret_cast<float4*>(&sW[s][wk][wc4 * 4]) = pw;
        __syncthreads();
        if (ch < IN_CH / BK - 1) {
            int kofs = (ch + 1) * BK;
            pa0 = __ldg(xr0 + kofs / 4);
            pa1 = __ldg(xr1 + kofs / 4);
            pw  = __ldg(reinterpret_cast<const float4*>(
                            W1 + (size_t)(kofs + wk) * HID_CH) + wc4);
        }
#pragma unroll
        for (int k = 0; k < BK; k++) {
            ulonglong2 aA = *reinterpret_cast<const ulonglong2*>(&sA[s][k][ty * 8]);
            ulonglong2 aB = *reinterpret_cast<const ulonglong2*>(&sA[s][k][ty * 8 + 4]);
            float4 wv = *reinterpret_cast<const float4*>(&sW[s][k][tx * 4]);
            unsigned long long w0 = pack2(wv.x, wv.x);
            unsigned long long w1 = pack2(wv.y, wv.y);
            unsigned long long w2 = pack2(wv.z, wv.z);
            unsigned long long w3 = pack2(wv.w, wv.w);
            acc[0][0] = fma2(aA.x, w0, acc[0][0]);
            acc[0][1] = fma2(aA.x, w1, acc[0][1]);
            acc[0][2] = fma2(aA.x, w2, acc[0][2]);
            acc[0][3] = fma2(aA.x, w3, acc[0][3]);
            acc[1][0] = fma2(aA.y, w0, acc[1][0]);
            acc[1][1] = fma2(aA.y, w1, acc[1][1]);
            acc[1][2] = fma2(aA.y, w2, acc[1][2]);
            acc[1][3] = fma2(aA.y, w3, acc[1][3]);
            acc[2][0] = fma2(aB.x, w0, acc[2][0]);
            acc[2][1] = fma2(aB.x, w1, acc[2][1]);
            acc[2][2] = fma2(aB.x, w2, acc[2][2]);
            acc[2][3] = fma2(aB.x, w3, acc[2][3]);
            acc[3][0] = fma2(aB.y, w0, acc[3][0]);
            acc[3][1] = fma2(aB.y, w1, acc[3][1]);
            acc[3][2] = fma2(aB.y, w2, acc[3][2]);
            acc[3][3] = fma2(aB.y, w3, acc[3][3]);
        }
    }
#pragma unroll
    for (int rp = 0; rp < 4; rp++) {
        int r = row0 + ty * 8 + rp * 2;
        float2 c0 = ull2f2(acc[rp][0]), c1 = ull2f2(acc[rp][1]);
        float2 c2 = ull2f2(acc[rp][2]), c3 = ull2f2(acc[rp][3]);
        if (r < N_NODES) {
            float4 lo = make_float4(c0.x, c1.x, c2.x, c3.x);
            *reinterpret_cast<float4*>(g_h1 + (size_t)r * HID_CH + tx * 4) = lo;
        }
        if (r + 1 < N_NODES) {
            float4 hi = make_float4(c0.y, c1.y, c2.y, c3.y);
            *reinterpret_cast<float4*>(g_h1 + (size_t)(r + 1) * HID_CH + tx * 4) = hi;
        }
    }
}

// ---------------- K1: gemm1a (blocks [0,391)) ∥ hist (rest) ----------------
__global__ __launch_bounds__(256) void k_g1a_hist(const float* __restrict__ x,
                                                  const float* __restrict__ W1,
                                                  const int* __restrict__ dst) {
    if (blockIdx.x < G1A_BLOCKS) {
        gemm1_body(blockIdx.x * BM, x, W1);
    } else {
        int e = (blockIdx.x - G1A_BLOCKS) * 256 + threadIdx.x;
        if (e < N_EDGES) atomicAdd(&g_deg[__ldg(dst + e)], 1);
    }
}

// ---------------- scan1: per-block inclusive scan (warp-shuffle) ----------------
__global__ __launch_bounds__(SCAN_B) void k_scan1() {
    __shared__ int swarp[32];
    int tid = threadIdx.x;
    int lane = tid & 31, wid = tid >> 5;
    int i = blockIdx.x * SCAN_B + tid;
    int v = (i < N_NODES) ? g_deg[i] : 0;
    int x = v;
#pragma unroll
    for (int o = 1; o < 32; o <<= 1) {
        int n = __shfl_up_sync(0xffffffffu, x, o);
        if (lane >= o) x += n;
    }
    if (lane == 31) swarp[wid] = x;
    __syncthreads();
    if (wid == 0) {
        int w = swarp[lane];
#pragma unroll
        for (int o = 1; o < 32; o <<= 1) {
            int n = __shfl_up_sync(0xffffffffu, w, o);
            if (lane >= o) w += n;
        }
        swarp[lane] = w;
    }
    __syncthreads();
    int incl = x + (wid > 0 ? swarp[wid - 1] : 0);
    if (i < N_NODES) g_incl[i] = incl;
    if (tid == SCAN_B - 1) g_bsum[blockIdx.x] = incl;
}

// ---------------- scan23: block-base reduce + final offsets + cursor prime ----------------
__global__ __launch_bounds__(SCAN_B) void k_scan23() {
    __shared__ int sred[32];
    __shared__ int s_base;
    int tid = threadIdx.x;
    int v = (tid < blockIdx.x) ? g_bsum[tid] : 0;   // blockIdx.x <= 97 < 128
#pragma unroll
    for (int o = 16; o; o >>= 1) v += __shfl_down_sync(0xffffffffu, v, o);
    if ((tid & 31) == 0) sred[tid >> 5] = v;
    __syncthreads();
    if (tid < 32) {
        int w = sred[tid];
#pragma unroll
        for (int o = 16; o; o >>= 1) w += __shfl_down_sync(0xffffffffu, w, o);
        if (tid == 0) s_base = w;
    }
    __syncthreads();
    int i = blockIdx.x * SCAN_B + tid;
    if (i < N_NODES) {
        int d = g_deg[i];
        int off = g_incl[i] - d + s_base;
        g_off[i] = off;
        g_cursor[i] = off;
        if (i == N_NODES - 1) g_off[N_NODES] = off + d;
    }
}

// ---------------- K2: gemm1b (blocks [0,391)) ∥ fill (rest) ----------------
__global__ __launch_bounds__(256) void k_g1b_fill(const float* __restrict__ x,
                                                  const float* __restrict__ W1,
                                                  const int* __restrict__ src,
                                                  const int* __restrict__ dst) {
    if (blockIdx.x < G1B_BLOCKS) {
        gemm1_body(G1B_ROW0 + blockIdx.x * BM, x, W1);
    } else {
        int e = (blockIdx.x - G1B_BLOCKS) * 256 + threadIdx.x;
        if (e < N_EDGES) {
            int d = __ldg(dst + e);
            int pos = atomicAdd(&g_cursor[d], 1);
            g_csr_src[pos] = __ldg(src + e);
        }
    }
}

// ---------------- agg1: act1 = relu(A @ h1 + b1); 2 edges per warp-load ----------------
__global__ __launch_bounds__(256) void k_agg1(const float* __restrict__ b1) {
    int t = blockIdx.x * 256 + threadIdx.x;
    int node = t >> 5;
    if (node >= N_NODES) return;
    int lane = t & 31;
    int half = lane >> 4;
    int q    = lane & 15;

    int beg = g_off[node];
    int dg  = g_off[node + 1] - beg;
    if (lane == 0) g_deg[node] = 0;      // restore zero-invariant for next call

    const float4* h1v = reinterpret_cast<const float4*>(g_h1);
    float4 a0{0,0,0,0}, a1{0,0,0,0}, a2{0,0,0,0}, a3{0,0,0,0};

    for (int base = 0; base < dg; base += 32) {
        int rem = dg - base;
        int idx = (lane < rem) ? __ldg(g_csr_src + beg + base + lane) : 0;
#pragma unroll
        for (int j = 0; j < 16; j += 4) {
            if (2 * j >= rem) break;     // warp-uniform
            int s0 = __shfl_sync(0xffffffffu, idx, 2 * j + 0 + half);
            int s1 = __shfl_sync(0xffffffffu, idx, 2 * j + 2 + half);
            int s2 = __shfl_sync(0xffffffffu, idx, 2 * j + 4 + half);
            int s3 = __shfl_sync(0xffffffffu, idx, 2 * j + 6 + half);
            if (2 * j + 0 + half < rem) {
                float4 v = __ldg(h1v + (size_t)s0 * 16 + q);
                a0.x += v.x; a0.y += v.y; a0.z += v.z; a0.w += v.w;
            }
            if (2 * j + 2 + half < rem) {
                float4 v = __ldg(h1v + (size_t)s1 * 16 + q);
                a1.x += v.x; a1.y += v.y; a1.z += v.z; a1.w += v.w;
            }
            if (2 * j + 4 + half < rem) {
                float4 v = __ldg(h1v + (size_t)s2 * 16 + q);
                a2.x += v.x; a2.y += v.y; a2.z += v.z; a2.w += v.w;
            }
            if (2 * j + 6 + half < rem) {
                float4 v = __ldg(h1v + (size_t)s3 * 16 + q);
                a3.x += v.x; a3.y += v.y; a3.z += v.z; a3.w += v.w;
            }
        }
    }
    float4 A;
    A.x = (a0.x + a1.x) + (a2.x + a3.x);
    A.y = (a0.y + a1.y) + (a2.y + a3.y);
    A.z = (a0.z + a1.z) + (a2.z + a3.z);
    A.w = (a0.w + a1.w) + (a2.w + a3.w);
    A.x += __shfl_xor_sync(0xffffffffu, A.x, 16);
    A.y += __shfl_xor_sync(0xffffffffu, A.y, 16);
    A.z += __shfl_xor_sync(0xffffffffu, A.z, 16);
    A.w += __shfl_xor_sync(0xffffffffu, A.w, 16);
    if (half == 0) {
        float4 b = __ldg(reinterpret_cast<const float4*>(b1) + q);
        A.x = fmaxf(A.x + b.x, 0.f);
        A.y = fmaxf(A.y + b.y, 0.f);
        A.z = fmaxf(A.z + b.z, 0.f);
        A.w = fmaxf(A.w + b.w, 0.f);
        reinterpret_cast<float4*>(g_act1)[(size_t)node * 16 + q] = A;
    }
}

// ---------------- gemm2: m2 = act1 @ W2 (64->32), double-buffered (R8-proven) ----------------
__global__ __launch_bounds__(256) void k_gemm2(const float* __restrict__ W2) {
    __shared__ __align__(16) float sA[2][BK][SA_PAD];
    __shared__ __align__(16) float sW[2][BK][CLS_CH];
    int tid = threadIdx.x;
    int tx = tid & 15;
    int ty = tid >> 4;
    int row0 = blockIdx.x * BM;
    int ar = tid >> 2, ac4 = tid & 3;
    int wk = tid >> 3, wc4 = tid & 7;
    int gr0 = min(row0 + ar,      N_NODES - 1);
    int gr1 = min(row0 + ar + 64, N_NODES - 1);

    float4 pa0, pa1, pw;
    pa0 = *reinterpret_cast<const float4*>(g_act1 + (size_t)gr0 * HID_CH + ac4 * 4);
    pa1 = *reinterpret_cast<const float4*>(g_act1 + (size_t)gr1 * HID_CH + ac4 * 4);
    if (tid < 128)
        pw = __ldg(reinterpret_cast<const float4*>(W2 + (size_t)wk * CLS_CH) + wc4);

    unsigned long long acc[4][2];
#pragma unroll
    for (int i = 0; i < 4; i++) { acc[i][0] = 0ull; acc[i][1] = 0ull; }

#pragma unroll 1
    for (int ch = 0; ch < HID_CH / BK; ch++) {
        int s = ch & 1;
        sA[s][ac4 * 4 + 0][ar] = pa0.x;
        sA[s][ac4 * 4 + 1][ar] = pa0.y;
        sA[s][ac4 * 4 + 2][ar] = pa0.z;
        sA[s][ac4 * 4 + 3][ar] = pa0.w;
        sA[s][ac4 * 4 + 0][ar + 64] = pa1.x;
        sA[s][ac4 * 4 + 1][ar + 64] = pa1.y;
        sA[s][ac4 * 4 + 2][ar + 64] = pa1.z;
        sA[s][ac4 * 4 + 3][ar + 64] = pa1.w;
        if (tid < 128)
            *reinterpret_cast<float4*>(&sW[s][wk][wc4 * 4]) = pw;
        __syncthreads();
        if (ch < HID_CH / BK - 1) {
            int kofs = (ch + 1) * BK;
            pa0 = *reinterpret_cast<const float4*>(
                g_act1 + (size_t)gr0 * HID_CH + kofs + ac4 * 4);
            pa1 = *reinterpret_cast<const float4*>(
                g_act1 + (size_t)gr1 * HID_CH + kofs + ac4 * 4);
            if (tid < 128)
                pw = __ldg(reinterpret_cast<const float4*>(
                               W2 + (size_t)(kofs + wk) * CLS_CH) + wc4);
        }
#pragma unroll
        for (int k = 0; k < BK; k++) {
            ulonglong2 aA = *reinterpret_cast<const ulonglong2*>(&sA[s][k][ty * 8]);
            ulonglong2 aB = *reinterpret_cast<const ulonglong2*>(&sA[s][k][ty * 8 + 4]);
            float2 wv = *reinterpret_cast<const float2*>(&sW[s][k][tx * 2]);
            unsigned long long w0 = pack2(wv.x, wv.x);
            unsigned long long w1 = pack2(wv.y, wv.y);
            acc[0][0] = fma2(aA.x, w0, acc[0][0]);
            acc[0][1] = fma2(aA.x, w1, acc[0][1]);
            acc[1][0] = fma2(aA.y, w0, acc[1][0]);
            acc[1][1] = fma2(aA.y, w1, acc[1][1]);
            acc[2][0] = fma2(aB.x, w0, acc[2][0]);
            acc[2][1] = fma2(aB.x, w1, acc[2][1]);
            acc[3][0] = fma2(aB.y, w0, acc[3][0]);
            acc[3][1] = fma2(aB.y, w1, acc[3][1]);
        }
    }
#pragma unroll
    for (int rp = 0; rp < 4; rp++) {
        int r = row0 + ty * 8 + rp * 2;
        float2 c0 = ull2f2(acc[rp][0]), c1 = ull2f2(acc[rp][1]);
        if (r < N_NODES) {
            float2 lo = make_float2(c0.x, c1.x);
            *reinterpret_cast<float2*>(g_m2 + (size_t)r * CLS_CH + tx * 2) = lo;
        }
        if (r + 1 < N_NODES) {
            float2 hi = make_float2(c0.y, c1.y);
            *reinterpret_cast<float2*>(g_m2 + (size_t)(r + 1) * CLS_CH + tx * 2) = hi;
        }
    }
}

// ---------------- agg2: out = sigmoid(A @ m2 + b2); 4 edges per warp-load ----------------
__global__ __launch_bounds__(256) void k_agg2(const float* __restrict__ b2,
                                              float* __restrict__ out) {
    int t = blockIdx.x * 256 + threadIdx.x;
    int node = t >> 5;
    if (node >= N_NODES) return;
    int lane = t & 31;
    int grp = lane >> 3;
    int q   = lane & 7;

    int beg = g_off[node];
    int dg  = g_off[node + 1] - beg;

    const float4* m2v = reinterpret_cast<const float4*>(g_m2);
    float4 a0{0,0,0,0}, a1{0,0,0,0}, a2{0,0,0,0}, a3{0,0,0,0};

    for (int base = 0; base < dg; base += 32) {
        int rem = dg - base;
        int idx = (lane < rem) ? __ldg(g_csr_src + beg + base + lane) : 0;
#pragma unroll
        for (int j = 0; j < 8; j += 4) {
            if (4 * j >= rem) break;     // warp-uniform
            int s0 = __shfl_sync(0xffffffffu, idx, 4 * (j + 0) + grp);
            int s1 = __shfl_sync(0xffffffffu, idx, 4 * (j + 1) + grp);
            int s2 = __shfl_sync(0xffffffffu, idx, 4 * (j + 2) + grp);
            int s3 = __shfl_sync(0xffffffffu, idx, 4 * (j + 3) + grp);
            if (4 * (j + 0) + grp < rem) {
                float4 v = __ldg(m2v + (size_t)s0 * 8 + q);
                a0.x += v.x; a0.y += v.y; a0.z += v.z; a0.w += v.w;
            }
            if (4 * (j + 1) + grp < rem) {
                float4 v = __ldg(m2v + (size_t)s1 * 8 + q);
                a1.x += v.x; a1.y += v.y; a1.z += v.z; a1.w += v.w;
            }
            if (4 * (j + 2) + grp < rem) {
                float4 v = __ldg(m2v + (size_t)s2 * 8 + q);
                a2.x += v.x; a2.y += v.y; a2.z += v.z; a2.w += v.w;
            }
            if (4 * (j + 3) + grp < rem) {
                float4 v = __ldg(m2v + (size_t)s3 * 8 + q);
                a3.x += v.x; a3.y += v.y; a3.z += v.z; a3.w += v.w;
            }
        }
    }
    float4 A;
    A.x = (a0.x + a1.x) + (a2.x + a3.x);
    A.y = (a0.y + a1.y) + (a2.y + a3.y);
    A.z = (a0.z + a1.z) + (a2.z + a3.z);
    A.w = (a0.w + a1.w) + (a2.w + a3.w);
    A.x += __shfl_xor_sync(0xffffffffu, A.x, 8);
    A.y += __shfl_xor_sync(0xffffffffu, A.y, 8);
    A.z += __shfl_xor_sync(0xffffffffu, A.z, 8);
    A.w += __shfl_xor_sync(0xffffffffu, A.w, 8);
    A.x += __shfl_xor_sync(0xffffffffu, A.x, 16);
    A.y += __shfl_xor_sync(0xffffffffu, A.y, 16);
    A.z += __shfl_xor_sync(0xffffffffu, A.z, 16);
    A.w += __shfl_xor_sync(0xffffffffu, A.w, 16);
    if (lane < 8) {
        float4 b = __ldg(reinterpret_cast<const float4*>(b2) + q);
        A.x = 1.f / (1.f + __expf(-(A.x + b.x)));
        A.y = 1.f / (1.f + __expf(-(A.y + b.y)));
        A.z = 1.f / (1.f + __expf(-(A.z + b.z)));
        A.w = 1.f / (1.f + __expf(-(A.w + b.w)));
        reinterpret_cast<float4*>(out)[(size_t)node * 8 + q] = A;
    }
}

extern "C" void kernel_launch(void* const* d_in, const int* in_sizes, int n_in,
                              void* d_out, int out_size) {
    const float* x  = (const float*)d_in[0];
    const int*   ei = (const int*)  d_in[1];
    const float* W1 = (const float*)d_in[2];
    const float* b1 = (const float*)d_in[3];
    const float* W2 = (const float*)d_in[4];
    const float* b2 = (const float*)d_in[5];
    float* out = (float*)d_out;
    const int* src = ei;
    const int* dst = ei + N_EDGES;

    k_g1a_hist<<<G1A_BLOCKS + HIST_BLOCKS, 256>>>(x, W1, dst);        // gemm1a ∥ hist
    k_scan1<<<NB, SCAN_B>>>();
    k_scan23<<<NB, SCAN_B>>>();
    k_g1b_fill<<<G1B_BLOCKS + HIST_BLOCKS, 256>>>(x, W1, src, dst);   // gemm1b ∥ fill  <- profiled (idx 3)
    k_agg1<<<(N_NODES * 32 + 255) / 256, 256>>>(b1);
    k_gemm2<<<(N_NODES + BM - 1) / BM, 256>>>(W2);
    k_agg2<<<(N_NODES * 32 + 255) / 256, 256>>>(b2, out);
}